// round 2
// baseline (speedup 1.0000x reference)
#include <cuda_runtime.h>
#include <math.h>

#define Bn 64
#define Tn 1024
#define Kn 128
#define TAG_START 126
#define TAG_STOP  127
#define NEGV -10000.0f

__device__ float g_partial[Bn];

#define FMA2(acc, x, y) \
    asm("fma.rn.f32x2 %0, %1, %2, %0;" : "+l"(acc) : "l"(x), "l"(y))

#define PACK2(dst, lo, hi) \
    asm("mov.b64 %0, {%1, %2};" : "=l"(dst) : "f"(lo), "f"(hi))

#define UNPACK2(lo, hi, src) \
    asm("mov.b64 {%0, %1}, %2;" : "=f"(lo), "=f"(hi) : "l"(src))

__global__ __launch_bounds__(128, 1) void crf_fwd_kernel(
    const float* __restrict__ feats,
    const int*   __restrict__ tags,
    const int*   __restrict__ lens,
    const float* __restrict__ trans)
{
    const int b = blockIdx.x;
    const int j = threadIdx.x;          // tag index, 0..127
    const float* fb = feats + (size_t)b * Tn * Kn;
    const int*   tb = tags + b * Tn;
    const int    len = lens[b];

    __shared__ __align__(16) float eAs[Kn];
    __shared__ float red[Kn];
    __shared__ float sh_v0;
    __shared__ float sh_gold;

    // ---------------- gold score (parallel over t) ----------------
    float gsum = 0.f;
    for (int t = j; t < Tn; t += Kn) {
        if (t < len)     gsum += fb[t * Kn + tb[t]];
        if (t < len - 1) gsum += trans[tb[t + 1] * Kn + tb[t]];
    }
    red[j] = gsum;
    __syncthreads();
    #pragma unroll
    for (int s = 64; s > 0; s >>= 1) {
        if (j < s) red[j] += red[j + s];
        __syncthreads();
    }
    if (j == 0) sh_gold = red[0];
    __syncthreads();

    // ---------------- precompute exp(trans) row j into registers ----------------
    unsigned long long eT2[64];
    #pragma unroll
    for (int i = 0; i < 64; i++) {
        float e0 = __expf(trans[j * Kn + 2 * i]);
        float e1 = __expf(trans[j * Kn + 2 * i + 1]);
        PACK2(eT2[i], e0, e1);
    }

    // ---------------- alpha init (t = 0) ----------------
    // alpha0[j] = NEG except alpha0[START] = feats[b,0,START].
    // Keep normalized a = alpha - c with c = feats[b,0,START].
    float c = fb[TAG_START];
    float a = (j == TAG_START) ? 0.f : (NEGV - c);

    // prefetch feat for t = 1
    float fnext = (len > 1) ? fb[Kn + j] : 0.f;

    // ---------------- sequential forward recursion ----------------
    for (int t = 1; t < len; t++) {
        float f = fnext;
        if (t + 1 < len) fnext = fb[(t + 1) * Kn + j];   // hide LDG under GEMV

        eAs[j] = __expf(a);
        __syncthreads();

        unsigned long long acc0 = 0ull, acc1 = 0ull, acc2 = 0ull, acc3 = 0ull;
        #pragma unroll
        for (int i = 0; i < 32; i++) {
            ulonglong2 p = *(const ulonglong2*)(eAs + 4 * i);   // LDS.128 broadcast
            if ((i & 1) == 0) {
                FMA2(acc0, p.x, eT2[2 * i]);
                FMA2(acc1, p.y, eT2[2 * i + 1]);
            } else {
                FMA2(acc2, p.x, eT2[2 * i]);
                FMA2(acc3, p.y, eT2[2 * i + 1]);
            }
        }
        float l0, h0, l1, h1, l2, h2, l3, h3;
        UNPACK2(l0, h0, acc0); UNPACK2(l1, h1, acc1);
        UNPACK2(l2, h2, acc2); UNPACK2(l3, h3, acc3);
        float dot = ((l0 + h0) + (l1 + h1)) + ((l2 + h2) + (l3 + h3));

        float v = f + __logf(dot);
        if (j == 0) sh_v0 = v;
        __syncthreads();            // also protects eAs for next iteration

        float v0 = sh_v0;
        a = v - v0;
        c += v0;
    }

    // ---------------- terminal logsumexp over K ----------------
    red[j] = a;
    __syncthreads();
    #pragma unroll
    for (int s = 64; s > 0; s >>= 1) {
        if (j < s) red[j] = fmaxf(red[j], red[j + s]);
        __syncthreads();
    }
    float m = red[0];
    __syncthreads();
    red[j] = __expf(a - m);
    __syncthreads();
    #pragma unroll
    for (int s = 64; s > 0; s >>= 1) {
        if (j < s) red[j] += red[j + s];
        __syncthreads();
    }
    if (j == 0) {
        float forward = c + m + __logf(red[0]);
        g_partial[b] = forward - sh_gold;
    }
}

__global__ void crf_mean_kernel(float* out)
{
    __shared__ float red[Bn];
    int j = threadIdx.x;
    red[j] = g_partial[j];
    __syncthreads();
    #pragma unroll
    for (int s = 32; s > 0; s >>= 1) {
        if (j < s) red[j] += red[j + s];
        __syncthreads();
    }
    if (j == 0) out[0] = red[0] * (1.0f / Bn);
}

extern "C" void kernel_launch(void* const* d_in, const int* in_sizes, int n_in,
                              void* d_out, int out_size)
{
    const float* feats = (const float*)d_in[0];
    const int*   tags  = (const int*)d_in[1];
    const int*   lens  = (const int*)d_in[2];
    const float* trans = (const float*)d_in[3];
    float* out = (float*)d_out;

    crf_fwd_kernel<<<Bn, Kn>>>(feats, tags, lens, trans);
    crf_mean_kernel<<<1, Bn>>>(out);
}

// round 3
// speedup vs baseline: 1.0899x; 1.0899x over previous
#include <cuda_runtime.h>
#include <math.h>

#define Bn 64
#define Tn 1024
#define Kn 128
#define TAG_START 126
#define TAG_STOP  127
#define NEGV -10000.0f
#define LOG2E 1.4426950408889634f
#define LN2   0.6931471805599453f

__device__ float g_partial[Bn];

#define FMA2(acc, x, y) \
    asm("fma.rn.f32x2 %0, %1, %2, %0;" : "+l"(acc) : "l"(x), "l"(y))

#define ADD2(dst, x, y) \
    asm("add.rn.f32x2 %0, %1, %2;" : "=l"(dst) : "l"(x), "l"(y))

#define PACK2(dst, lo, hi) \
    asm("mov.b64 %0, {%1, %2};" : "=l"(dst) : "f"(lo), "f"(hi))

#define UNPACK2(lo, hi, src) \
    asm("mov.b64 {%0, %1}, %2;" : "=f"(lo), "=f"(hi) : "l"(src))

__device__ __forceinline__ float ex2(float x) {
    float r; asm("ex2.approx.f32 %0, %1;" : "=f"(r) : "f"(x)); return r;
}
__device__ __forceinline__ float lg2(float x) {
    float r; asm("lg2.approx.f32 %0, %1;" : "=f"(r) : "f"(x)); return r;
}

__global__ __launch_bounds__(128, 1) void crf_fwd_kernel(
    const float* __restrict__ feats,
    const int*   __restrict__ tags,
    const int*   __restrict__ lens,
    const float* __restrict__ trans)
{
    const int b = blockIdx.x;
    const int j = threadIdx.x;          // tag index, 0..127
    const float* fb = feats + (size_t)b * Tn * Kn;
    const int*   tb = tags + b * Tn;
    const int    len = lens[b];

    __shared__ __align__(16) float eAs[2][Kn];
    __shared__ float sv0[2];
    __shared__ float red[Kn];
    __shared__ float sh_gold;

    // ---------------- gold score (parallel over t, natural log domain) ----------------
    float gsum = 0.f;
    for (int t = j; t < Tn; t += Kn) {
        if (t < len)     gsum += fb[t * Kn + tb[t]];
        if (t < len - 1) gsum += trans[tb[t + 1] * Kn + tb[t]];
    }
    red[j] = gsum;
    __syncthreads();
    #pragma unroll
    for (int s = 64; s > 0; s >>= 1) {
        if (j < s) red[j] += red[j + s];
        __syncthreads();
    }
    if (j == 0) sh_gold = red[0];

    // ---------------- precompute exp(trans) row j into registers ----------------
    unsigned long long eT2[64];
    #pragma unroll
    for (int i = 0; i < 64; i++) {
        float e0 = ex2(trans[j * Kn + 2 * i]     * LOG2E);
        float e1 = ex2(trans[j * Kn + 2 * i + 1] * LOG2E);
        PACK2(eT2[i], e0, e1);
    }

    // ---------------- alpha init (t = 0), base-2 log domain ----------------
    // alpha0[j] = NEG except alpha0[START] = feats[b,0,START].
    // a2 = alpha*LOG2E - c2 with c2 = feats[b,0,START]*LOG2E.
    float f0s = fb[TAG_START];
    float c2 = f0s * LOG2E;
    float a2 = (j == TAG_START) ? 0.f : (NEGV - f0s) * LOG2E;

    eAs[0][j] = ex2(a2);
    if (j == 0) sv0[0] = 0.f;

    // prefetch feat for t = 1
    float fnext = (len > 1) ? fb[Kn + j] : 0.f;

    // ---------------- sequential forward recursion (1 barrier/step) ----------------
    for (int t = 1; t < len; t++) {
        const int cur = (t - 1) & 1;
        const int nxt = t & 1;
        float f2 = fnext * LOG2E;
        if (t + 1 < len) fnext = fb[(t + 1) * Kn + j];   // hide LDG under GEMV

        __syncthreads();             // publishes eAs[cur], sv0[cur]
        float s = sv0[cur];          // lagged normalizer (latency hidden by GEMV)

        const ulonglong2* __restrict__ pA = (const ulonglong2*)eAs[cur];
        unsigned long long acc0 = 0ull, acc1 = 0ull, acc2 = 0ull, acc3 = 0ull;
        #pragma unroll
        for (int i = 0; i < 32; i++) {
            ulonglong2 p = pA[i];                       // LDS.128 broadcast
            if ((i & 1) == 0) {
                FMA2(acc0, p.x, eT2[2 * i]);
                FMA2(acc1, p.y, eT2[2 * i + 1]);
            } else {
                FMA2(acc2, p.x, eT2[2 * i]);
                FMA2(acc3, p.y, eT2[2 * i + 1]);
            }
        }
        unsigned long long s01, s23, sall;
        ADD2(s01, acc0, acc1);
        ADD2(s23, acc2, acc3);
        ADD2(sall, s01, s23);
        float lo, hi;
        UNPACK2(lo, hi, sall);
        float dot = lo + hi;

        float v2 = f2 + lg2(dot);
        float a2n = v2 - s;
        c2 += s;
        eAs[nxt][j] = ex2(a2n);
        if (j == 0) sv0[nxt] = a2n;
        a2 = a2n;
    }

    // ---------------- terminal logsumexp over K (base-2) ----------------
    __syncthreads();
    red[j] = a2;
    __syncthreads();
    #pragma unroll
    for (int s = 64; s > 0; s >>= 1) {
        if (j < s) red[j] = fmaxf(red[j], red[j + s]);
        __syncthreads();
    }
    float m = red[0];
    __syncthreads();
    red[j] = ex2(a2 - m);
    __syncthreads();
    #pragma unroll
    for (int s = 64; s > 0; s >>= 1) {
        if (j < s) red[j] += red[j + s];
        __syncthreads();
    }
    if (j == 0) {
        float forward = (c2 + m + lg2(red[0])) * LN2;
        g_partial[b] = forward - sh_gold;
    }
}

__global__ void crf_mean_kernel(float* out)
{
    __shared__ float red[Bn];
    int j = threadIdx.x;
    red[j] = g_partial[j];
    __syncthreads();
    #pragma unroll
    for (int s = 32; s > 0; s >>= 1) {
        if (j < s) red[j] += red[j + s];
        __syncthreads();
    }
    if (j == 0) out[0] = red[0] * (1.0f / Bn);
}

extern "C" void kernel_launch(void* const* d_in, const int* in_sizes, int n_in,
                              void* d_out, int out_size)
{
    const float* feats = (const float*)d_in[0];
    const int*   tags  = (const int*)d_in[1];
    const int*   lens  = (const int*)d_in[2];
    const float* trans = (const float*)d_in[3];
    float* out = (float*)d_out;

    crf_fwd_kernel<<<Bn, Kn>>>(feats, tags, lens, trans);
    crf_mean_kernel<<<1, Bn>>>(out);
}

// round 4
// speedup vs baseline: 1.1343x; 1.0407x over previous
#include <cuda_runtime.h>
#include <math.h>

#define Bn 64
#define Tn 1024
#define Kn 128
#define TAG_START 126
#define TAG_STOP  127
#define NEGV -10000.0f
#define LOG2E 1.4426950408889634f
#define LN2   0.6931471805599453f

__device__ float g_partial[Bn];
__device__ unsigned int g_count = 0;

#define FMA2(acc, x, y) \
    asm("fma.rn.f32x2 %0, %1, %2, %0;" : "+l"(acc) : "l"(x), "l"(y))

#define ADD2(dst, x, y) \
    asm("add.rn.f32x2 %0, %1, %2;" : "=l"(dst) : "l"(x), "l"(y))

#define PACK2(dst, lo, hi) \
    asm("mov.b64 %0, {%1, %2};" : "=l"(dst) : "f"(lo), "f"(hi))

#define UNPACK2(lo, hi, src) \
    asm("mov.b64 {%0, %1}, %2;" : "=f"(lo), "=f"(hi) : "l"(src))

__device__ __forceinline__ float ex2(float x) {
    float r; asm("ex2.approx.f32 %0, %1;" : "=f"(r) : "f"(x)); return r;
}
__device__ __forceinline__ float lg2(float x) {
    float r; asm("lg2.approx.f32 %0, %1;" : "=f"(r) : "f"(x)); return r;
}

__global__ __launch_bounds__(128, 1) void crf_fwd_kernel(
    const float* __restrict__ feats,
    const int*   __restrict__ tags,
    const int*   __restrict__ lens,
    const float* __restrict__ trans,
    float*       __restrict__ out)
{
    const int b = blockIdx.x;
    const int j = threadIdx.x;          // tag index, 0..127
    const float* fb = feats + (size_t)b * Tn * Kn;
    const int*   tb = tags + b * Tn;
    const int    len = lens[b];

    __shared__ __align__(16) float eAs[2][Kn];
    __shared__ float sv0[2];            // lagged power-of-2 scale
    __shared__ int   se[2];             // its exponent (to accumulate)
    __shared__ float red[Kn];
    __shared__ float sh_gold;
    __shared__ int   sh_last;

    // ---------------- gold score (parallel over t, natural log) ----------------
    float gsum = 0.f;
    for (int t = j; t < Tn; t += Kn) {
        if (t < len)     gsum += fb[t * Kn + tb[t]];
        if (t < len - 1) gsum += trans[tb[t + 1] * Kn + tb[t]];
    }
    red[j] = gsum;
    __syncthreads();
    #pragma unroll
    for (int s = 64; s > 0; s >>= 1) {
        if (j < s) red[j] += red[j + s];
        __syncthreads();
    }
    if (j == 0) sh_gold = red[0];

    // ---------------- precompute exp(trans) row j into registers ----------------
    unsigned long long eT2[64];
    #pragma unroll
    for (int i = 0; i < 64; i++) {
        float e0 = ex2(trans[j * Kn + 2 * i]     * LOG2E);
        float e1 = ex2(trans[j * Kn + 2 * i + 1] * LOG2E);
        PACK2(eT2[i], e0, e1);
    }

    // ---------------- init (t = 0), linear domain ----------------
    // w[j] = exp(alpha0[j]) * 2^(-c2f): w[START]=1, others 0.
    float f0s = fb[TAG_START];
    float c2f = f0s * LOG2E;            // fractional part of exponent offset
    int   c2i = 0;                      // integer part (exact)
    eAs[0][j] = (j == TAG_START) ? 1.f : 0.f;
    if (j == 0) { sv0[0] = 1.f; se[0] = 0; }

    // depth-3 feat prefetch: fA = feat[t], pA = feat[t+1], pB = feat[t+2] in flight
    float fA = (1 < len) ? fb[1 * Kn + j] : 0.f;
    float pA = (2 < len) ? fb[2 * Kn + j] : 0.f;
    float pB = (3 < len) ? fb[3 * Kn + j] : 0.f;
    float ef = ex2(fA * LOG2E);         // exp(feat[1][j])

    // ---------------- sequential forward recursion ----------------
    for (int t = 1; t < len; t++) {
        const int cur = (t - 1) & 1;
        const int nxt = t & 1;

        // issue LDG for feat[t+3] (~2 steps of latency cover)
        float pC = (t + 3 < len) ? fb[(t + 3) * Kn + j] : 0.f;
        // MUFU for next step's exp(feat), fully hidden under this step's GEMV
        float ef_next = ex2(pA * LOG2E);

        __syncthreads();                 // publishes eAs[cur], sv0[cur], se[cur]
        float sc  = sv0[cur];
        float efs = ef * sc;             // off the critical chain
        if (j == 0) c2i += se[cur];

        const ulonglong2* __restrict__ pV = (const ulonglong2*)eAs[cur];
        unsigned long long acc0 = 0ull, acc1 = 0ull, acc2 = 0ull, acc3 = 0ull;
        #pragma unroll
        for (int i = 0; i < 32; i++) {
            ulonglong2 p = pV[i];                       // LDS.128 broadcast
            if ((i & 1) == 0) {
                FMA2(acc0, p.x, eT2[2 * i]);
                FMA2(acc1, p.y, eT2[2 * i + 1]);
            } else {
                FMA2(acc2, p.x, eT2[2 * i]);
                FMA2(acc3, p.y, eT2[2 * i + 1]);
            }
        }
        unsigned long long s01, s23, sall;
        ADD2(s01, acc0, acc1);
        ADD2(s23, acc2, acc3);
        ADD2(sall, s01, s23);
        float lo, hi;
        UNPACK2(lo, hi, sall);
        float dot = lo + hi;

        float w = dot * efs;             // single FMUL after the dot
        eAs[nxt][j] = w;
        if (j == 0) {
            int e = (__float_as_int(w) >> 23) - 127;     // w > 0, normal
            sv0[nxt] = __int_as_float((127 - e) << 23);  // 2^-e exactly
            se[nxt]  = e;
        }

        ef = ef_next; fA = pA; pA = pB; pB = pC;
    }

    // ---------------- terminal: log2(sum w) + exponent offset ----------------
    __syncthreads();
    float wfin = eAs[(len - 1) & 1][j];
    red[j] = wfin;
    __syncthreads();
    #pragma unroll
    for (int s = 64; s > 0; s >>= 1) {
        if (j < s) red[j] += red[j + s];
        __syncthreads();
    }
    if (j == 0) {
        float forward = ((float)c2i + c2f + lg2(red[0])) * LN2;
        g_partial[b] = forward - sh_gold;
        __threadfence();
        unsigned int f = atomicAdd(&g_count, 1);
        sh_last = (f == Bn - 1);
    }
    __syncthreads();

    // last block to finish reduces the mean
    if (sh_last) {
        __threadfence();
        red[j] = (j < Bn) ? g_partial[j] : 0.f;
        __syncthreads();
        #pragma unroll
        for (int s = 32; s > 0; s >>= 1) {
            if (j < s) red[j] += red[j + s];
            __syncthreads();
        }
        if (j == 0) {
            out[0] = red[0] * (1.0f / Bn);
            g_count = 0;                 // reset for next launch / graph replay
        }
    }
}

extern "C" void kernel_launch(void* const* d_in, const int* in_sizes, int n_in,
                              void* d_out, int out_size)
{
    const float* feats = (const float*)d_in[0];
    const int*   tags  = (const int*)d_in[1];
    const int*   lens  = (const int*)d_in[2];
    const float* trans = (const float*)d_in[3];
    float* out = (float*)d_out;

    crf_fwd_kernel<<<Bn, Kn>>>(feats, tags, lens, trans, out);
}

// round 5
// speedup vs baseline: 1.1574x; 1.0204x over previous
#include <cuda_runtime.h>
#include <math.h>

#define Bn 64
#define Tn 1024
#define Kn 128
#define NT 256
#define TAG_START 126
#define TAG_STOP  127
#define NEGV -10000.0f
#define LOG2E 1.4426950408889634f
#define LN2   0.6931471805599453f

__device__ float g_partial[Bn];
__device__ unsigned int g_count = 0;

#define FMA2(acc, x, y) \
    asm("fma.rn.f32x2 %0, %1, %2, %0;" : "+l"(acc) : "l"(x), "l"(y))

#define ADD2(dst, x, y) \
    asm("add.rn.f32x2 %0, %1, %2;" : "=l"(dst) : "l"(x), "l"(y))

#define PACK2(dst, lo, hi) \
    asm("mov.b64 %0, {%1, %2};" : "=l"(dst) : "f"(lo), "f"(hi))

#define UNPACK2(lo, hi, src) \
    asm("mov.b64 {%0, %1}, %2;" : "=f"(lo), "=f"(hi) : "l"(src))

__device__ __forceinline__ float ex2(float x) {
    float r; asm("ex2.approx.f32 %0, %1;" : "=f"(r) : "f"(x)); return r;
}
__device__ __forceinline__ float lg2(float x) {
    float r; asm("lg2.approx.f32 %0, %1;" : "=f"(r) : "f"(x)); return r;
}

__global__ __launch_bounds__(NT, 1) void crf_fwd_kernel(
    const float* __restrict__ feats,
    const int*   __restrict__ tags,
    const int*   __restrict__ lens,
    const float* __restrict__ trans,
    float*       __restrict__ out)
{
    const int b   = blockIdx.x;
    const int tid = threadIdx.x;
    const int w   = tid >> 5;          // warp 0..7
    const int l   = tid & 31;          // lane
    const int half = l >> 4;           // 0: inputs [0,64), 1: inputs [64,128)
    const int jj  = (w << 4) | (l & 15);   // output tag 0..127 (pair (l, l^16) shares jj)

    const float* fb = feats + (size_t)b * Tn * Kn;
    const int*   tb = tags + b * Tn;
    const int    len = lens[b];

    __shared__ __align__(16) float eAs[2][Kn];
    __shared__ float sv0[2];           // lagged power-of-2 scale
    __shared__ float red[NT];
    __shared__ float sh_gold;
    __shared__ float sh_ci;            // accumulated exponent (from lane 16)
    __shared__ int   sh_last;

    // ---------------- gold score (parallel over t, natural log) ----------------
    float gsum = 0.f;
    for (int t = tid; t < Tn; t += NT) {
        if (t < len)     gsum += fb[t * Kn + tb[t]];
        if (t < len - 1) gsum += trans[tb[t + 1] * Kn + tb[t]];
    }
    red[tid] = gsum;
    __syncthreads();
    #pragma unroll
    for (int s = NT / 2; s > 0; s >>= 1) {
        if (tid < s) red[tid] += red[tid + s];
        __syncthreads();
    }
    if (tid == 0) sh_gold = red[0];

    // ---------------- precompute exp(trans) half-row into 32 regs ----------------
    unsigned long long eT2[32];
    const float* trow = trans + jj * Kn + half * 64;
    #pragma unroll
    for (int i = 0; i < 32; i++) {
        float e0 = ex2(trow[2 * i]     * LOG2E);
        float e1 = ex2(trow[2 * i + 1] * LOG2E);
        PACK2(eT2[i], e0, e1);
    }

    // ---------------- init (t = 0), linear domain ----------------
    float f0s = fb[TAG_START];
    float c2f = f0s * LOG2E;
    if (l < 16) eAs[0][jj] = (jj == TAG_START) ? 1.f : 0.f;
    if (tid == 0) { sv0[0] = 1.f; sh_ci = 0.f; }
    int prev_e = 0;                    // exponent applied via sv0 (lane (0,16) tracks)
    int c2i = 0;

    // depth-3 feat prefetch (all lanes load; duplicates hit L1)
    float fA = (1 < len) ? fb[1 * Kn + jj] : 0.f;
    float pA = (2 < len) ? fb[2 * Kn + jj] : 0.f;
    float pB = (3 < len) ? fb[3 * Kn + jj] : 0.f;
    float ef = ex2(fA * LOG2E);

    // ---------------- sequential forward recursion (1 barrier/step) ----------------
    for (int t = 1; t < len; t++) {
        const int cur = (t - 1) & 1;
        const int nxt = t & 1;

        float pC = (t + 3 < len) ? fb[(t + 3) * Kn + jj] : 0.f;
        float ef_next = ex2(pA * LOG2E);        // hidden under this step's GEMV

        __syncthreads();                        // publishes eAs[cur], sv0[cur]
        float sc  = sv0[cur];
        float efs = ef * sc;                    // off the critical chain

        const ulonglong2* __restrict__ pV =
            (const ulonglong2*)(eAs[cur] + half * 64);
        unsigned long long acc0 = 0ull, acc1 = 0ull;
        #pragma unroll
        for (int i = 0; i < 16; i++) {
            ulonglong2 p = pV[i];               // LDS.128 broadcast
            FMA2(acc0, p.x, eT2[2 * i]);
            FMA2(acc1, p.y, eT2[2 * i + 1]);
        }
        unsigned long long sall;
        ADD2(sall, acc0, acc1);
        float lo, hi;
        UNPACK2(lo, hi, sall);
        float part = lo + hi;

        float other = __shfl_xor_sync(0xffffffffu, part, 16);
        float dot = part + other;

        float wv = dot * efs;
        if (l < 16) eAs[nxt][jj] = wv;          // store half publishes
        if (w == 0 && l == 16) {                // redundant w[0] lane: renorm publish
            c2i += prev_e;
            int e = (__float_as_int(wv) >> 23) - 127;      // wv > 0, normal
            sv0[nxt] = __int_as_float((127 - e) << 23);    // 2^-e exactly
            prev_e = e;
        }

        ef = ef_next; fA = pA; pA = pB; pB = pC;
    }

    if (w == 0 && l == 16) sh_ci = (float)c2i;

    // ---------------- terminal: log2(sum w) + exponent offset ----------------
    __syncthreads();
    red[tid] = (l < 16) ? eAs[(len - 1) & 1][jj] : 0.f;
    __syncthreads();
    #pragma unroll
    for (int s = NT / 2; s > 0; s >>= 1) {
        if (tid < s) red[tid] += red[tid + s];
        __syncthreads();
    }
    if (tid == 0) {
        float forward = (sh_ci + c2f + lg2(red[0])) * LN2;
        g_partial[b] = forward - sh_gold;
        __threadfence();
        unsigned int f = atomicAdd(&g_count, 1);
        sh_last = (f == Bn - 1);
    }
    __syncthreads();

    // last block to finish reduces the mean
    if (sh_last) {
        __threadfence();
        red[tid] = (tid < Bn) ? g_partial[tid] : 0.f;
        __syncthreads();
        #pragma unroll
        for (int s = 32; s > 0; s >>= 1) {
            if (tid < s) red[tid] += red[tid + s];
            __syncthreads();
        }
        if (tid == 0) {
            out[0] = red[0] * (1.0f / Bn);
            g_count = 0;               // reset for graph replay
        }
    }
}

extern "C" void kernel_launch(void* const* d_in, const int* in_sizes, int n_in,
                              void* d_out, int out_size)
{
    const float* feats = (const float*)d_in[0];
    const int*   tags  = (const int*)d_in[1];
    const int*   lens  = (const int*)d_in[2];
    const float* trans = (const float*)d_in[3];
    float* out = (float*)d_out;

    crf_fwd_kernel<<<Bn, NT>>>(feats, tags, lens, trans, out);
}